// round 2
// baseline (speedup 1.0000x reference)
#include <cuda_runtime.h>
#include <math.h>
#include <stdint.h>

#define A_N 49104
#define B_N 8
#define C_N 80
#define K_N 256
#define IMG 512.0f
#define TOTAL (B_N * A_N)      // 392832
#define NBIN 32768
#define ROW4 20                // 80 floats = 20 float4 per anchor row
#define ROW4P 21               // padded stride in float4 (84 floats) -> conflict-free

// -------- device scratch --------
__device__ float    g_scores[TOTAL];
__device__ unsigned g_hist1[B_N * NBIN];
__device__ unsigned g_hist2[B_N * NBIN];
__device__ unsigned g_T1[B_N];
__device__ unsigned g_rem1[B_N];
__device__ float4   g_topb[B_N * K_N];
__device__ float    g_tops[B_N * K_N];
__device__ int      g_topl[B_N * K_N];

// ============================================================
// zero histograms
// ============================================================
__global__ void zeroHist() {
    int i = blockIdx.x * blockDim.x + threadIdx.x;
    if (i < B_N * NBIN) { g_hist1[i] = 0u; g_hist2[i] = 0u; }
}

// ============================================================
// Stage A: class max + sigmoid + threshold + 15-bit histogram.
// Shared-staged, fully coalesced reads of cls.
// ============================================================
__global__ void stageA(const float* __restrict__ cls) {
    extern __shared__ float4 sh4[];   // 256 * 21 float4 = 86016 B
    const int tid = threadIdx.x;
    const int tileA = blockIdx.x * 256;
    const int nA = min(256, TOTAL - tileA);
    const float4* src = reinterpret_cast<const float4*>(cls) + (size_t)tileA * ROW4;

    if (nA == 256) {
#pragma unroll
        for (int k = 0; k < ROW4; k += 4) {
            float4 r0 = src[(k + 0) * 256 + tid];
            float4 r1 = src[(k + 1) * 256 + tid];
            float4 r2 = src[(k + 2) * 256 + tid];
            float4 r3 = src[(k + 3) * 256 + tid];
            int p0 = (k + 0) * 256 + tid;
            int p1 = (k + 1) * 256 + tid;
            int p2 = (k + 2) * 256 + tid;
            int p3 = (k + 3) * 256 + tid;
            sh4[(p0 / ROW4) * ROW4P + (p0 % ROW4)] = r0;
            sh4[(p1 / ROW4) * ROW4P + (p1 % ROW4)] = r1;
            sh4[(p2 / ROW4) * ROW4P + (p2 % ROW4)] = r2;
            sh4[(p3 / ROW4) * ROW4P + (p3 % ROW4)] = r3;
        }
    } else {
        int nf4 = nA * ROW4;
        for (int f = tid; f < nf4; f += 256) {
            float4 r = src[f];
            sh4[(f / ROW4) * ROW4P + (f % ROW4)] = r;
        }
    }
    __syncthreads();

    if (tid < nA) {
        const float4* row = sh4 + tid * ROW4P;
        float m = -INFINITY;
#pragma unroll
        for (int i = 0; i < ROW4; i++) {
            float4 v = row[i];
            m = fmaxf(m, fmaxf(fmaxf(v.x, v.y), fmaxf(v.z, v.w)));
        }
        float score = 1.0f / (1.0f + expf(-m));
        if (!(score > 0.01f)) score = 0.0f;

        int g = tileA + tid;
        int b = g / A_N;
        g_scores[g] = score;

        unsigned bin = __float_as_uint(score) >> 15;          // < 32768 (score < 2)
        unsigned key = ((unsigned)b << 15) | bin;             // == index into g_hist1
        unsigned peers = __match_any_sync(0xffffffffu, key);
        int leader = __ffs(peers) - 1;
        if ((tid & 31) == leader)
            atomicAdd(&g_hist1[key], (unsigned)__popc(peers));
    }
}

// ============================================================
// suffix-select helper: find bin (from top) where cumulative
// count crosses `target`. hist has 32768 bins. 1024 threads.
// ============================================================
__device__ void suffix_select(const unsigned* __restrict__ h, unsigned target,
                              unsigned* csum, unsigned* ws,
                              unsigned* out_bin, unsigned* out_rem) {
    int tid = threadIdx.x;
    unsigned s = 0;
#pragma unroll 8
    for (int i = 0; i < 32; i++) s += h[tid * 32 + i];
    csum[tid] = s;
    __syncthreads();
    if (tid < 32) {
        unsigned t = 0;
#pragma unroll 8
        for (int i = 0; i < 32; i++) t += csum[tid * 32 + i];
        ws[tid] = t;
    }
    __syncthreads();
    if (tid == 0) {
        unsigned cum = 0;
        int w = 31;
        for (; w > 0; w--) { if (cum + ws[w] >= target) break; cum += ws[w]; }
        int c = w * 32 + 31;
        for (; c > w * 32; c--) { if (cum + csum[c] >= target) break; cum += csum[c]; }
        int bbin = c * 32 + 31;
        for (; bbin > c * 32; bbin--) { if (cum + h[bbin] >= target) break; cum += h[bbin]; }
        *out_bin = (unsigned)bbin;
        *out_rem = target - cum;
    }
    __syncthreads();
}

__global__ __launch_bounds__(1024) void select1() {
    __shared__ unsigned csum[1024], ws[32], obin, orem;
    int b = blockIdx.x;
    suffix_select(g_hist1 + b * NBIN, K_N, csum, ws, &obin, &orem);
    if (threadIdx.x == 0) { g_T1[b] = obin; g_rem1[b] = orem; }
}

// ============================================================
// Pass 2 histogram over low 15 bits, elements matching T1
// ============================================================
__global__ void hist2k() {
    int g = blockIdx.x * blockDim.x + threadIdx.x;
    if (g >= TOTAL) return;
    int b = g / A_N;
    unsigned k = __float_as_uint(g_scores[g]);
    if ((k >> 15) == g_T1[b])
        atomicAdd(&g_hist2[b * NBIN + (k & 0x7FFFu)], 1u);
}

// ============================================================
// Collect: exact threshold (S2), gather >T + lowest-index ==T,
// bitonic sort 256, recompute label + box for winners.
// ============================================================
__global__ __launch_bounds__(1024) void collect(const float* __restrict__ cls,
                                                const float* __restrict__ regs,
                                                const float* __restrict__ anchors) {
    int b = blockIdx.x;
    int tid = threadIdx.x;
    int lane = tid & 31, wid = tid >> 5;

    __shared__ unsigned csum[1024], ws[32];
    __shared__ unsigned sh_bin, sh_need;
    suffix_select(g_hist2 + b * NBIN, g_rem1[b], csum, ws, &sh_bin, &sh_need);

    __shared__ unsigned sh_T;
    __shared__ unsigned long long top[K_N];
    __shared__ unsigned gt_cnt;
    if (tid == 0) {
        sh_T = (g_T1[b] << 15) | sh_bin;
        gt_cnt = 0;
    }
    __syncthreads();
    unsigned T = sh_T;
    unsigned need = sh_need;          // entries equal to T to take (lowest idx)
    unsigned G = K_N - need;          // == count of keys strictly > T

    const float* sc = g_scores + b * A_N;
    for (int a = tid; a < A_N; a += 1024) {
        unsigned k = __float_as_uint(sc[a]);
        if (k > T) {
            unsigned p = atomicAdd(&gt_cnt, 1u);
            top[p] = (((unsigned long long)k) << 32) | (0xFFFFFFFFu - (unsigned)a);
        }
    }
    __syncthreads();

    // ordered compaction of ==T (ascending index, early exit)
    __shared__ unsigned eqidx[K_N];
    __shared__ unsigned wq[32];
    __shared__ unsigned eqc;
    if (tid == 0) eqc = 0;
    __syncthreads();
    for (int base = 0; base < A_N; base += 1024) {
        int a = base + tid;
        bool pred = (a < A_N) && (__float_as_uint(sc[a]) == T);
        unsigned m = __ballot_sync(0xffffffffu, pred);
        if (lane == 0) wq[wid] = __popc(m);
        __syncthreads();
        if (tid == 0) {
            unsigned cb = eqc;
#pragma unroll
            for (int w = 0; w < 32; w++) { unsigned c = wq[w]; wq[w] = cb; cb += c; }
            eqc = cb;
        }
        __syncthreads();
        if (pred) {
            unsigned pos = wq[wid] + __popc(m & ((1u << lane) - 1u));
            if (pos < need) eqidx[pos] = (unsigned)a;
        }
        __syncthreads();
        if (eqc >= need) break;
    }
    if (tid < need)
        top[G + tid] = (((unsigned long long)T) << 32) | (0xFFFFFFFFu - eqidx[tid]);
    __syncthreads();

    // bitonic sort 256 descending by (score bits, ~index)
    for (unsigned kk = 2; kk <= K_N; kk <<= 1) {
        for (unsigned j = kk >> 1; j > 0; j >>= 1) {
            if (tid < K_N) {
                unsigned ixj = tid ^ j;
                if (ixj > (unsigned)tid) {
                    unsigned long long x = top[tid], y = top[ixj];
                    bool descseg = ((tid & kk) == 0);
                    bool doswap = descseg ? (x < y) : (x > y);
                    if (doswap) { top[tid] = y; top[ixj] = x; }
                }
            }
            __syncthreads();
        }
    }

    // gather: 4 threads per entry recompute argmax label; lane 0 decodes box
    int e = tid >> 2, j = tid & 3;
    unsigned long long v = top[e];
    unsigned k = (unsigned)(v >> 32);
    unsigned a = 0xFFFFFFFFu - (unsigned)(v & 0xFFFFFFFFu);
    const float4* row = reinterpret_cast<const float4*>(cls) +
                        ((size_t)b * A_N + a) * ROW4;
    float m = -INFINITY;
    int arg = 0;
#pragma unroll
    for (int q0 = 0; q0 < 5; q0++) {
        int q = j + 4 * q0;
        float4 x = row[q];
        int c = 4 * q;
        if (x.x > m) { m = x.x; arg = c; }
        if (x.y > m) { m = x.y; arg = c + 1; }
        if (x.z > m) { m = x.z; arg = c + 2; }
        if (x.w > m) { m = x.w; arg = c + 3; }
    }
#pragma unroll
    for (int off = 1; off < 4; off <<= 1) {
        float mo = __shfl_xor_sync(0xffffffffu, m, off);
        int ao = __shfl_xor_sync(0xffffffffu, arg, off);
        if (mo > m || (mo == m && ao < arg)) { m = mo; arg = ao; }
    }
    if (j == 0) {
        int o = b * K_N + e;
        g_tops[o] = __uint_as_float(k);
        g_topl[o] = arg;
        float4 an = reinterpret_cast<const float4*>(anchors)[a];
        float aw = an.z - an.x, ah = an.w - an.y;
        float acx = an.x + 0.5f * aw, acy = an.y + 0.5f * ah;
        float4 rg = reinterpret_cast<const float4*>(regs)[(size_t)b * A_N + a];
        float cx = acx + rg.x * aw;
        float cy = acy + rg.y * ah;
        float dw = fminf(fmaxf(rg.z, -4.0f), 4.0f);
        float dh = fminf(fmaxf(rg.w, -4.0f), 4.0f);
        float w = aw * expf(dw);
        float h = ah * expf(dh);
        float x1 = fminf(fmaxf(cx - 0.5f * w, 0.0f), IMG);
        float y1 = fminf(fmaxf(cy - 0.5f * h, 0.0f), IMG);
        float x2 = fminf(fmaxf(cx + 0.5f * w, 0.0f), IMG);
        float y2 = fminf(fmaxf(cy + 0.5f * h, 0.0f), IMG);
        g_topb[o] = make_float4(x1, y1, x2, y2);
    }
}

// ============================================================
// Stage C: sequential NMS on 256 sorted candidates + output
// ============================================================
__global__ __launch_bounds__(K_N) void stageC(float* __restrict__ out, int out_size) {
    int b = blockIdx.x;
    int tid = threadIdx.x;

    __shared__ float4 bx[K_N];
    __shared__ float sc[K_N];
    __shared__ unsigned msk[K_N][8];
    __shared__ unsigned keepw[8];

    bx[tid] = g_topb[b * K_N + tid];
    sc[tid] = g_tops[b * K_N + tid];
    __syncthreads();

    float4 me = bx[tid];
    float myarea = fmaxf(me.z - me.x, 0.0f) * fmaxf(me.w - me.y, 0.0f);
    unsigned words[8] = {0u, 0u, 0u, 0u, 0u, 0u, 0u, 0u};
#pragma unroll 4
    for (int j = 0; j < K_N; j++) {
        float4 o = bx[j];
        float ix1 = fmaxf(me.x, o.x);
        float iy1 = fmaxf(me.y, o.y);
        float ix2 = fminf(me.z, o.z);
        float iy2 = fminf(me.w, o.w);
        float iw = fmaxf(ix2 - ix1, 0.0f);
        float ih = fmaxf(iy2 - iy1, 0.0f);
        float inter = iw * ih;
        float oarea = fmaxf(o.z - o.x, 0.0f) * fmaxf(o.w - o.y, 0.0f);
        float uni = myarea + oarea - inter;
        float iou = inter / fmaxf(uni, 1e-8f);
        if (iou > 0.5f) words[j >> 5] |= 1u << (j & 31);
    }
#pragma unroll
    for (int w = 0; w < 8; w++) msk[tid][w] = words[w];
    __syncthreads();

    if (tid == 0) {
#pragma unroll
        for (int w = 0; w < 8; w++) keepw[w] = 0u;
        for (int i = 0; i < K_N; i++) {
            bool k0 = sc[i] > 0.0f;
            unsigned sup = 0u;
            int wi = i >> 5;
            for (int w = 0; w < wi; w++) sup |= msk[i][w] & keepw[w];
            unsigned below = (1u << (i & 31)) - 1u;
            sup |= msk[i][wi] & keepw[wi] & below;
            if (k0 && sup == 0u) keepw[wi] |= 1u << (i & 31);
        }
    }
    __syncthreads();

    bool kp = (keepw[tid >> 5] >> (tid & 31)) & 1u;
    float kf = kp ? 1.0f : 0.0f;
    int base = b * K_N + tid;

    out[base * 5 + 0] = me.x * kf;
    out[base * 5 + 1] = me.y * kf;
    out[base * 5 + 2] = me.z * kf;
    out[base * 5 + 3] = me.w * kf;
    out[base * 5 + 4] = sc[tid] * kf;
    if (out_size >= B_N * K_N * 5 + B_N * K_N)
        out[B_N * K_N * 5 + base] = (float)g_topl[base];
    if (out_size >= B_N * K_N * 5 + 2 * B_N * K_N)
        out[B_N * K_N * 5 + B_N * K_N + base] = kf;
}

// ============================================================
extern "C" void kernel_launch(void* const* d_in, const int* in_sizes, int n_in,
                              void* d_out, int out_size) {
    const float* cls = nullptr;
    const float* regs = nullptr;
    const float* anchors = nullptr;
    for (int i = 0; i < n_in; i++) {
        if (in_sizes[i] == B_N * A_N * C_N) cls = (const float*)d_in[i];
        else if (in_sizes[i] == B_N * A_N * 4) regs = (const float*)d_in[i];
        else if (in_sizes[i] == A_N * 4) anchors = (const float*)d_in[i];
    }
    if (!cls || !regs || !anchors) return;

    float* out = (float*)d_out;

    const int SMEM_A = 256 * ROW4P * sizeof(float4);  // 86016
    cudaFuncSetAttribute(stageA, cudaFuncAttributeMaxDynamicSharedMemorySize, SMEM_A);

    zeroHist<<<(B_N * NBIN + 1023) / 1024, 1024>>>();
    stageA<<<(TOTAL + 255) / 256, 256, SMEM_A>>>(cls);
    select1<<<B_N, 1024>>>();
    hist2k<<<(TOTAL + 1023) / 1024, 1024>>>();
    collect<<<B_N, 1024>>>(cls, regs, anchors);
    stageC<<<B_N, K_N>>>(out, out_size);
}